// round 1
// baseline (speedup 1.0000x reference)
#include <cuda_runtime.h>

// Problem constants
#define BB 2048
#define TT 200
#define DD 4
#define HH 256
#define GG 1024   // 4*H, PyTorch gate order i,f,g,o in blocks of 256
#define MM 16     // batch rows per CTA
#define NCTA (BB / MM)   // 128 CTAs
#define OO 6
#define HP 18     // padded smem row length (floats) for h tiles

// Transposed weights + combined biases (filled by prep kernel each launch)
__device__ float g_Wt_hh0[HH * GG];  // [k][g]
__device__ float g_Wt_ih1[HH * GG];
__device__ float g_Wt_hh1[HH * GG];
__device__ float g_b0[GG];
__device__ float g_b1[GG];

// ---- packed f32x2 helpers (Blackwell FFMA2 path) ----
__device__ __forceinline__ unsigned long long fma2(unsigned long long a,
                                                   unsigned long long b,
                                                   unsigned long long c) {
    unsigned long long d;
    asm("fma.rn.f32x2 %0, %1, %2, %3;" : "=l"(d) : "l"(a), "l"(b), "l"(c));
    return d;
}
__device__ __forceinline__ unsigned long long dup2(float v) {
    unsigned long long d;
    unsigned r = __float_as_uint(v);
    asm("mov.b64 %0, {%1, %1};" : "=l"(d) : "r"(r));
    return d;
}
__device__ __forceinline__ unsigned long long pack2(float a, float b) {
    unsigned long long d;
    asm("mov.b64 %0, {%1, %2};" : "=l"(d)
        : "r"(__float_as_uint(a)), "r"(__float_as_uint(b)));
    return d;
}
__device__ __forceinline__ void unpack2(unsigned long long v, float& a, float& b) {
    unsigned x, y;
    asm("mov.b64 {%0, %1}, %2;" : "=r"(x), "=r"(y) : "l"(v));
    a = __uint_as_float(x);
    b = __uint_as_float(y);
}

__device__ __forceinline__ float sigf(float x) {
    return 1.0f / (1.0f + __expf(-x));
}

// -------- prep: transpose weights to [k][g] layout, combine biases --------
__global__ void prep_kernel(const float* __restrict__ W_hh0,
                            const float* __restrict__ W_ih1,
                            const float* __restrict__ W_hh1,
                            const float* __restrict__ b_ih0,
                            const float* __restrict__ b_hh0,
                            const float* __restrict__ b_ih1,
                            const float* __restrict__ b_hh1) {
    int idx = blockIdx.x * blockDim.x + threadIdx.x;
    int stride = gridDim.x * blockDim.x;
    for (int t = idx; t < HH * GG; t += stride) {
        int k = t >> 10;        // / 1024
        int g = t & (GG - 1);   // % 1024
        g_Wt_hh0[t] = W_hh0[g * HH + k];
        g_Wt_ih1[t] = W_ih1[g * HH + k];
        g_Wt_hh1[t] = W_hh1[g * HH + k];
    }
    if (idx < GG) {
        g_b0[idx] = b_ih0[idx] + b_hh0[idx];
        g_b1[idx] = b_ih1[idx] + b_hh1[idx];
    }
}

// -------- main persistent LSTM kernel: one CTA = 16 batch rows, all 200 steps --------
__global__ __launch_bounds__(256, 1)
void lstm_kernel(const float* __restrict__ x,
                 const float* __restrict__ W_ih0,
                 const float* __restrict__ W_fc,
                 const float* __restrict__ b_fc,
                 float* __restrict__ out) {
    __shared__ float hs1[HH][HP];   // layer0 hidden, hs1[k][m]
    __shared__ float hs2[HH][HP];   // layer1 hidden
    __shared__ float xs[MM][DD];

    const int j = threadIdx.x;            // hidden unit owned by this thread
    const int row0 = blockIdx.x * MM;

    // Per-thread constants
    float wih0[4][DD];
    float bias0[4], bias1[4];
#pragma unroll
    for (int q = 0; q < 4; q++) {
        bias0[q] = g_b0[j + 256 * q];
        bias1[q] = g_b1[j + 256 * q];
#pragma unroll
        for (int d = 0; d < DD; d++)
            wih0[q][d] = W_ih0[(j + 256 * q) * DD + d];
    }

    float c1[MM], c2[MM];
#pragma unroll
    for (int m = 0; m < MM; m++) {
        c1[m] = 0.0f;
        c2[m] = 0.0f;
        hs1[j][m] = 0.0f;
        hs2[j][m] = 0.0f;
    }
    __syncthreads();

    for (int t = 0; t < TT; t++) {
        // ---- stage x[row0..row0+15, t, :] ----
        if (j < MM * DD)
            xs[j >> 2][j & 3] = x[(row0 + (j >> 2)) * (TT * DD) + t * DD + (j & 3)];
        __syncthreads();  // S1: xs visible; hs1(t-1)/hs2(t-1) stable

        // ================= Layer 0 =================
        unsigned long long acc[4][MM / 2];
#pragma unroll
        for (int q = 0; q < 4; q++)
#pragma unroll
            for (int i = 0; i < MM / 2; i++) {
                float z0 = bias0[q], z1 = bias0[q];
#pragma unroll
                for (int d = 0; d < DD; d++) {
                    z0 = fmaf(wih0[q][d], xs[2 * i][d], z0);
                    z1 = fmaf(wih0[q][d], xs[2 * i + 1][d], z1);
                }
                acc[q][i] = pack2(z0, z1);
            }

        {
            const float* p = g_Wt_hh0 + j;
#pragma unroll 4
            for (int k = 0; k < HH; k++) {
                unsigned long long w[4];
#pragma unroll
                for (int q = 0; q < 4; q++) w[q] = dup2(p[256 * q]);
                p += GG;
#pragma unroll
                for (int i = 0; i < MM / 2; i++) {
                    unsigned long long hv =
                        *reinterpret_cast<const unsigned long long*>(&hs1[k][2 * i]);
#pragma unroll
                    for (int q = 0; q < 4; q++) acc[q][i] = fma2(w[q], hv, acc[q][i]);
                }
            }
        }

        // activations + cell update for layer 0
        float hnew[MM];
#pragma unroll
        for (int i = 0; i < MM / 2; i++) {
            float zi0, zi1, zf0, zf1, zg0, zg1, zo0, zo1;
            unpack2(acc[0][i], zi0, zi1);
            unpack2(acc[1][i], zf0, zf1);
            unpack2(acc[2][i], zg0, zg1);
            unpack2(acc[3][i], zo0, zo1);
            {
                int m = 2 * i;
                float ig = sigf(zi0), fg = sigf(zf0), gg = tanhf(zg0), og = sigf(zo0);
                float c = fmaf(fg, c1[m], ig * gg);
                c1[m] = c;
                hnew[m] = og * tanhf(c);
            }
            {
                int m = 2 * i + 1;
                float ig = sigf(zi1), fg = sigf(zf1), gg = tanhf(zg1), og = sigf(zo1);
                float c = fmaf(fg, c1[m], ig * gg);
                c1[m] = c;
                hnew[m] = og * tanhf(c);
            }
        }
        __syncthreads();  // S2: all layer-0 reads of hs1 done
#pragma unroll
        for (int m = 0; m < MM; m++) hs1[j][m] = hnew[m];
        __syncthreads();  // S3: hs1(t) visible

        // ================= Layer 1 =================
#pragma unroll
        for (int q = 0; q < 4; q++)
#pragma unroll
            for (int i = 0; i < MM / 2; i++)
                acc[q][i] = pack2(bias1[q], bias1[q]);

        {
            const float* pi = g_Wt_ih1 + j;
            const float* ph = g_Wt_hh1 + j;
#pragma unroll 2
            for (int k = 0; k < HH; k++) {
                unsigned long long wi[4], wh[4];
#pragma unroll
                for (int q = 0; q < 4; q++) {
                    wi[q] = dup2(pi[256 * q]);
                    wh[q] = dup2(ph[256 * q]);
                }
                pi += GG;
                ph += GG;
#pragma unroll
                for (int i = 0; i < MM / 2; i++) {
                    unsigned long long hv1 =
                        *reinterpret_cast<const unsigned long long*>(&hs1[k][2 * i]);
                    unsigned long long hv2 =
                        *reinterpret_cast<const unsigned long long*>(&hs2[k][2 * i]);
#pragma unroll
                    for (int q = 0; q < 4; q++) {
                        acc[q][i] = fma2(wi[q], hv1, acc[q][i]);
                        acc[q][i] = fma2(wh[q], hv2, acc[q][i]);
                    }
                }
            }
        }

#pragma unroll
        for (int i = 0; i < MM / 2; i++) {
            float zi0, zi1, zf0, zf1, zg0, zg1, zo0, zo1;
            unpack2(acc[0][i], zi0, zi1);
            unpack2(acc[1][i], zf0, zf1);
            unpack2(acc[2][i], zg0, zg1);
            unpack2(acc[3][i], zo0, zo1);
            {
                int m = 2 * i;
                float ig = sigf(zi0), fg = sigf(zf0), gg = tanhf(zg0), og = sigf(zo0);
                float c = fmaf(fg, c2[m], ig * gg);
                c2[m] = c;
                hnew[m] = og * tanhf(c);
            }
            {
                int m = 2 * i + 1;
                float ig = sigf(zi1), fg = sigf(zf1), gg = tanhf(zg1), og = sigf(zo1);
                float c = fmaf(fg, c2[m], ig * gg);
                c2[m] = c;
                hnew[m] = og * tanhf(c);
            }
        }
        __syncthreads();  // S4: all layer-1 reads of hs2 done
#pragma unroll
        for (int m = 0; m < MM; m++) hs2[j][m] = hnew[m];
        // next iteration's S1 orders these writes before next layer-1 reads
    }
    __syncthreads();

    // ---- FC epilogue: out[row, o] = b_fc[o] + sum_k h2_last[row,k] * W_fc[o,k] ----
    if (j < MM * OO) {
        int m = j / OO;
        int o = j % OO;
        float s = b_fc[o];
#pragma unroll 4
        for (int k = 0; k < HH; k++)
            s = fmaf(hs2[k][m], W_fc[o * HH + k], s);
        out[(row0 + m) * OO + o] = s;
    }
}

extern "C" void kernel_launch(void* const* d_in, const int* in_sizes, int n_in,
                              void* d_out, int out_size) {
    const float* x     = (const float*)d_in[0];
    const float* W_ih0 = (const float*)d_in[1];
    const float* W_hh0 = (const float*)d_in[2];
    const float* b_ih0 = (const float*)d_in[3];
    const float* b_hh0 = (const float*)d_in[4];
    const float* W_ih1 = (const float*)d_in[5];
    const float* W_hh1 = (const float*)d_in[6];
    const float* b_ih1 = (const float*)d_in[7];
    const float* b_hh1 = (const float*)d_in[8];
    const float* W_fc  = (const float*)d_in[9];
    const float* b_fc  = (const float*)d_in[10];
    float* out = (float*)d_out;

    prep_kernel<<<256, 256>>>(W_hh0, W_ih1, W_hh1, b_ih0, b_hh0, b_ih1, b_hh1);
    lstm_kernel<<<NCTA, 256>>>(x, W_ih0, W_fc, b_fc, out);
}

// round 2
// speedup vs baseline: 1.1316x; 1.1316x over previous
#include <cuda_runtime.h>

// Problem constants
#define BB 2048
#define TT 200
#define DD 4
#define HH 256
#define GG 1024   // 4*H, gate order i,f,g,o in blocks of 256
#define MM 16     // batch rows per CTA
#define NCTA (BB / MM)   // 128 CTAs
#define MH 8      // rows per thread (half of MM)
#define OO 6
#define HP 20     // padded smem row length (floats), 80B = 16B-aligned

// Transposed weights + combined biases (filled by prep kernel each launch)
__device__ float g_Wt_hh0[HH * GG];  // [k][g]
__device__ float g_Wt_ih1[HH * GG];
__device__ float g_Wt_hh1[HH * GG];
__device__ float g_b0[GG];
__device__ float g_b1[GG];

// ---- packed f32x2 helpers ----
__device__ __forceinline__ unsigned long long fma2(unsigned long long a,
                                                   unsigned long long b,
                                                   unsigned long long c) {
    unsigned long long d;
    asm("fma.rn.f32x2 %0, %1, %2, %3;" : "=l"(d) : "l"(a), "l"(b), "l"(c));
    return d;
}
__device__ __forceinline__ unsigned long long dup2(float v) {
    unsigned long long d;
    unsigned r = __float_as_uint(v);
    asm("mov.b64 %0, {%1, %1};" : "=l"(d) : "r"(r));
    return d;
}
__device__ __forceinline__ unsigned long long pack2(float a, float b) {
    unsigned long long d;
    asm("mov.b64 %0, {%1, %2};" : "=l"(d)
        : "r"(__float_as_uint(a)), "r"(__float_as_uint(b)));
    return d;
}
__device__ __forceinline__ void unpack2(unsigned long long v, float& a, float& b) {
    unsigned x, y;
    asm("mov.b64 {%0, %1}, %2;" : "=r"(x), "=r"(y) : "l"(v));
    a = __uint_as_float(x);
    b = __uint_as_float(y);
}

__device__ __forceinline__ float sigf(float x) {
    return 1.0f / (1.0f + __expf(-x));
}

// -------- prep: transpose weights to [k][g] layout, combine biases --------
__global__ void prep_kernel(const float* __restrict__ W_hh0,
                            const float* __restrict__ W_ih1,
                            const float* __restrict__ W_hh1,
                            const float* __restrict__ b_ih0,
                            const float* __restrict__ b_hh0,
                            const float* __restrict__ b_ih1,
                            const float* __restrict__ b_hh1) {
    int idx = blockIdx.x * blockDim.x + threadIdx.x;
    int stride = gridDim.x * blockDim.x;
    for (int t = idx; t < HH * GG; t += stride) {
        int k = t >> 10;
        int g = t & (GG - 1);
        g_Wt_hh0[t] = W_hh0[g * HH + k];
        g_Wt_ih1[t] = W_ih1[g * HH + k];
        g_Wt_hh1[t] = W_hh1[g * HH + k];
    }
    if (idx < GG) {
        g_b0[idx] = b_ih0[idx] + b_hh0[idx];
        g_b1[idx] = b_ih1[idx] + b_hh1[idx];
    }
}

// -------- main LSTM kernel: 512 threads = (256 hidden units) x (2 batch halves) --------
__global__ __launch_bounds__(512, 1)
void lstm_kernel(const float* __restrict__ x,
                 const float* __restrict__ W_ih0,
                 const float* __restrict__ W_fc,
                 const float* __restrict__ b_fc,
                 float* __restrict__ out) {
    __shared__ float hs1[HH][HP];   // layer0 hidden, hs1[k][m]
    __shared__ float hs2[HH][HP];   // layer1 hidden
    __shared__ float xs[MM][DD];

    const int tid  = threadIdx.x;
    const int j    = tid & (HH - 1);    // hidden unit
    const int half = tid >> 8;          // batch half (0/1); warp-uniform
    const int mb   = half * MH;         // first batch row (within CTA) for this thread
    const int row0 = blockIdx.x * MM;

    // Per-thread constants
    float wih0[4][DD];
    float bias0[4], bias1[4];
#pragma unroll
    for (int q = 0; q < 4; q++) {
        bias0[q] = g_b0[j + 256 * q];
        bias1[q] = g_b1[j + 256 * q];
#pragma unroll
        for (int d = 0; d < DD; d++)
            wih0[q][d] = W_ih0[(j + 256 * q) * DD + d];
    }

    float c1[MH], c2[MH];
#pragma unroll
    for (int m = 0; m < MH; m++) {
        c1[m] = 0.0f;
        c2[m] = 0.0f;
        hs1[j][mb + m] = 0.0f;
        hs2[j][mb + m] = 0.0f;
    }
    __syncthreads();

    for (int t = 0; t < TT; t++) {
        // ---- stage x[row0..row0+15, t, :] ----
        if (tid < MM * DD)
            xs[tid >> 2][tid & 3] =
                x[(row0 + (tid >> 2)) * (TT * DD) + t * DD + (tid & 3)];
        __syncthreads();  // S1: xs visible; hs1(t-1)/hs2(t-1) stable

        // ================= Layer 0 =================
        unsigned long long acc[4][MH / 2];
#pragma unroll
        for (int q = 0; q < 4; q++)
#pragma unroll
            for (int i = 0; i < MH / 2; i++) {
                float z0 = bias0[q], z1 = bias0[q];
#pragma unroll
                for (int d = 0; d < DD; d++) {
                    z0 = fmaf(wih0[q][d], xs[mb + 2 * i][d], z0);
                    z1 = fmaf(wih0[q][d], xs[mb + 2 * i + 1][d], z1);
                }
                acc[q][i] = pack2(z0, z1);
            }

        {
            const float* p = g_Wt_hh0 + j;
#pragma unroll 4
            for (int k = 0; k < HH; k++) {
                unsigned long long w[4];
#pragma unroll
                for (int q = 0; q < 4; q++) w[q] = dup2(p[256 * q]);
                p += GG;
                // 8 h-values for this half: two float4 broadcasts
                float4 hv0 = *reinterpret_cast<const float4*>(&hs1[k][mb]);
                float4 hv1 = *reinterpret_cast<const float4*>(&hs1[k][mb + 4]);
                unsigned long long hp[4];
                hp[0] = pack2(hv0.x, hv0.y);
                hp[1] = pack2(hv0.z, hv0.w);
                hp[2] = pack2(hv1.x, hv1.y);
                hp[3] = pack2(hv1.z, hv1.w);
#pragma unroll
                for (int i = 0; i < MH / 2; i++)
#pragma unroll
                    for (int q = 0; q < 4; q++)
                        acc[q][i] = fma2(w[q], hp[i], acc[q][i]);
            }
        }

        // activations + cell update for layer 0
        float hnew[MH];
#pragma unroll
        for (int i = 0; i < MH / 2; i++) {
            float zi0, zi1, zf0, zf1, zg0, zg1, zo0, zo1;
            unpack2(acc[0][i], zi0, zi1);
            unpack2(acc[1][i], zf0, zf1);
            unpack2(acc[2][i], zg0, zg1);
            unpack2(acc[3][i], zo0, zo1);
            {
                int m = 2 * i;
                float ig = sigf(zi0), fg = sigf(zf0), gg = tanhf(zg0), og = sigf(zo0);
                float c = fmaf(fg, c1[m], ig * gg);
                c1[m] = c;
                hnew[m] = og * tanhf(c);
            }
            {
                int m = 2 * i + 1;
                float ig = sigf(zi1), fg = sigf(zf1), gg = tanhf(zg1), og = sigf(zo1);
                float c = fmaf(fg, c1[m], ig * gg);
                c1[m] = c;
                hnew[m] = og * tanhf(c);
            }
        }
        __syncthreads();  // S2: all layer-0 reads of hs1 done
        {
            float4 s0 = make_float4(hnew[0], hnew[1], hnew[2], hnew[3]);
            float4 s1 = make_float4(hnew[4], hnew[5], hnew[6], hnew[7]);
            *reinterpret_cast<float4*>(&hs1[j][mb]) = s0;
            *reinterpret_cast<float4*>(&hs1[j][mb + 4]) = s1;
        }
        __syncthreads();  // S3: hs1(t) visible

        // ================= Layer 1 =================
#pragma unroll
        for (int q = 0; q < 4; q++)
#pragma unroll
            for (int i = 0; i < MH / 2; i++)
                acc[q][i] = pack2(bias1[q], bias1[q]);

        {
            const float* pi = g_Wt_ih1 + j;
            const float* ph = g_Wt_hh1 + j;
#pragma unroll 2
            for (int k = 0; k < HH; k++) {
                unsigned long long wi[4], wh[4];
#pragma unroll
                for (int q = 0; q < 4; q++) {
                    wi[q] = dup2(pi[256 * q]);
                    wh[q] = dup2(ph[256 * q]);
                }
                pi += GG;
                ph += GG;
                float4 a0 = *reinterpret_cast<const float4*>(&hs1[k][mb]);
                float4 a1 = *reinterpret_cast<const float4*>(&hs1[k][mb + 4]);
                float4 b0 = *reinterpret_cast<const float4*>(&hs2[k][mb]);
                float4 b1 = *reinterpret_cast<const float4*>(&hs2[k][mb + 4]);
                unsigned long long h1p[4], h2p[4];
                h1p[0] = pack2(a0.x, a0.y);
                h1p[1] = pack2(a0.z, a0.w);
                h1p[2] = pack2(a1.x, a1.y);
                h1p[3] = pack2(a1.z, a1.w);
                h2p[0] = pack2(b0.x, b0.y);
                h2p[1] = pack2(b0.z, b0.w);
                h2p[2] = pack2(b1.x, b1.y);
                h2p[3] = pack2(b1.z, b1.w);
#pragma unroll
                for (int i = 0; i < MH / 2; i++)
#pragma unroll
                    for (int q = 0; q < 4; q++) {
                        acc[q][i] = fma2(wi[q], h1p[i], acc[q][i]);
                        acc[q][i] = fma2(wh[q], h2p[i], acc[q][i]);
                    }
            }
        }

#pragma unroll
        for (int i = 0; i < MH / 2; i++) {
            float zi0, zi1, zf0, zf1, zg0, zg1, zo0, zo1;
            unpack2(acc[0][i], zi0, zi1);
            unpack2(acc[1][i], zf0, zf1);
            unpack2(acc[2][i], zg0, zg1);
            unpack2(acc[3][i], zo0, zo1);
            {
                int m = 2 * i;
                float ig = sigf(zi0), fg = sigf(zf0), gg = tanhf(zg0), og = sigf(zo0);
                float c = fmaf(fg, c2[m], ig * gg);
                c2[m] = c;
                hnew[m] = og * tanhf(c);
            }
            {
                int m = 2 * i + 1;
                float ig = sigf(zi1), fg = sigf(zf1), gg = tanhf(zg1), og = sigf(zo1);
                float c = fmaf(fg, c2[m], ig * gg);
                c2[m] = c;
                hnew[m] = og * tanhf(c);
            }
        }
        __syncthreads();  // S4: all layer-1 reads of hs2 done
        {
            float4 s0 = make_float4(hnew[0], hnew[1], hnew[2], hnew[3]);
            float4 s1 = make_float4(hnew[4], hnew[5], hnew[6], hnew[7]);
            *reinterpret_cast<float4*>(&hs2[j][mb]) = s0;
            *reinterpret_cast<float4*>(&hs2[j][mb + 4]) = s1;
        }
        // next iteration's S1 orders these writes before next layer-1 reads
    }
    __syncthreads();

    // ---- FC epilogue: out[row, o] = b_fc[o] + sum_k h2_last[row,k] * W_fc[o,k] ----
    if (tid < MM * OO) {
        int m = tid / OO;
        int o = tid % OO;
        float s = b_fc[o];
#pragma unroll 4
        for (int k = 0; k < HH; k++)
            s = fmaf(hs2[k][m], W_fc[o * HH + k], s);
        out[(row0 + m) * OO + o] = s;
    }
}

extern "C" void kernel_launch(void* const* d_in, const int* in_sizes, int n_in,
                              void* d_out, int out_size) {
    const float* x     = (const float*)d_in[0];
    const float* W_ih0 = (const float*)d_in[1];
    const float* W_hh0 = (const float*)d_in[2];
    const float* b_ih0 = (const float*)d_in[3];
    const float* b_hh0 = (const float*)d_in[4];
    const float* W_ih1 = (const float*)d_in[5];
    const float* W_hh1 = (const float*)d_in[6];
    const float* b_ih1 = (const float*)d_in[7];
    const float* b_hh1 = (const float*)d_in[8];
    const float* W_fc  = (const float*)d_in[9];
    const float* b_fc  = (const float*)d_in[10];
    float* out = (float*)d_out;

    prep_kernel<<<256, 256>>>(W_hh0, W_ih1, W_hh1, b_ih0, b_hh0, b_ih1, b_hh1);
    lstm_kernel<<<NCTA, 512>>>(x, W_ih0, W_fc, b_fc, out);
}